// round 16
// baseline (speedup 1.0000x reference)
#include <cuda_runtime.h>
#include <cuda_fp16.h>
#include <cstdint>

#define B_ 4
#define T_ 2048
#define D_ 512
#define H_ 8
#define DH 64
#define M_ (B_*T_)              // 8192 rows
#define LN_EPS 1e-8f

// exp(s/8 - 5) = 2^(s*log2e/8 - 5*log2e); the s*log2e/8 factor is folded into Wq/bq.
#define QK_LOG2E_8 0.1803368801111204f
#define SHIFT_L2   (-7.2134752044448169f)

// ---------------- scratch (device globals: no allocation allowed) -------------
__device__ __half g_X16[3*M_*D_];        // fp16 queries/keys/values
__device__ __half g_W16[3*D_*D_];        // fp16 Wq(scaled)/Wk/Wv
__device__ __half g_Q16[M_*D_];          // pre-scaled by log2e/8
__device__ __half g_K16[M_*D_];
__device__ __half g_V16[M_*D_];
__device__ __half g_V16t[B_*H_*DH*T_];   // [bh][d][t]
__device__ float  g_O[M_*D_];
__device__ float  g_qmask[M_];
__device__ __half g_kmask16[M_];         // exp2-domain offset: SHIFT_L2 or -1e4

// ---------------- helpers -----------------------------------------------------
__device__ __forceinline__ float warp_sum32(float v) {
    #pragma unroll
    for (int o = 16; o > 0; o >>= 1) v += __shfl_xor_sync(0xffffffffu, v, o);
    return v;
}

__device__ __forceinline__ uint32_t s2u(const void* p) {
    uint32_t a;
    asm("{ .reg .u64 t; cvta.to.shared.u64 t, %1; cvt.u32.u64 %0, t; }" : "=r"(a) : "l"(p));
    return a;
}

__device__ __forceinline__ uint32_t pack_half2(float lo, float hi) {
    uint32_t r;
    asm("cvt.rn.f16x2.f32 %0, %1, %2;" : "=r"(r) : "f"(hi), "f"(lo));
    return r;
}

// p = 2^(s + koff) for two packed values: CVT + HADD2 + MUFU
__device__ __forceinline__ uint32_t exp2_h2_add(float lo, float hi, uint32_t off2) {
    uint32_t h = pack_half2(lo, hi);
    uint32_t s, r;
    asm("add.rn.f16x2 %0, %1, %2;" : "=r"(s) : "r"(h), "r"(off2));
    asm("ex2.approx.f16x2 %0, %1;" : "=r"(r) : "r"(s));
    return r;
}

#define ONES_H2 0x3C003C00u   // half2(1.0, 1.0)

__device__ __forceinline__ void ldsm4(uint32_t* r, uint32_t addr) {
    asm volatile("ldmatrix.sync.aligned.m8n8.x4.shared.b16 {%0,%1,%2,%3}, [%4];"
        : "=r"(r[0]), "=r"(r[1]), "=r"(r[2]), "=r"(r[3]) : "r"(addr));
}

__device__ __forceinline__ void ldsm4t(uint32_t* r, uint32_t addr) {
    asm volatile("ldmatrix.sync.aligned.m8n8.x4.trans.shared.b16 {%0,%1,%2,%3}, [%4];"
        : "=r"(r[0]), "=r"(r[1]), "=r"(r[2]), "=r"(r[3]) : "r"(addr));
}

__device__ __forceinline__ void mma16816(float* c, const uint32_t* a,
                                         uint32_t b0, uint32_t b1) {
    asm volatile(
        "mma.sync.aligned.m16n8k16.row.col.f32.f16.f16.f32 "
        "{%0,%1,%2,%3}, {%4,%5,%6,%7}, {%8,%9}, {%0,%1,%2,%3};"
        : "+f"(c[0]), "+f"(c[1]), "+f"(c[2]), "+f"(c[3])
        : "r"(a[0]), "r"(a[1]), "r"(a[2]), "r"(a[3]), "r"(b0), "r"(b1));
}

__device__ __forceinline__ void cp16(uint32_t smem_dst, const void* gsrc) {
    asm volatile("cp.async.cg.shared.global [%0], [%1], 16;"
        :: "r"(smem_dst), "l"(__cvta_generic_to_global(gsrc)) : "memory");
}
#define CP_COMMIT() asm volatile("cp.async.commit_group;" ::: "memory")
#define CP_WAIT(n)  asm volatile("cp.async.wait_group %0;" :: "n"(n) : "memory")

// ---------------- prep: fp32 -> fp16 X + masks --------------------------------
__global__ __launch_bounds__(128) void prep_kernel(const float* __restrict__ queries,
                                                   const float* __restrict__ keys,
                                                   const float* __restrict__ values) {
    int row = blockIdx.x;
    int tid = threadIdx.x;
    size_t off = (size_t)row*D_ + tid*4;
    float4 qv = *(const float4*)&queries[off];
    float4 kv = *(const float4*)&keys[off];
    float4 vv = *(const float4*)&values[off];
    uint2 qp = make_uint2(pack_half2(qv.x, qv.y), pack_half2(qv.z, qv.w));
    uint2 kp = make_uint2(pack_half2(kv.x, kv.y), pack_half2(kv.z, kv.w));
    uint2 vp = make_uint2(pack_half2(vv.x, vv.y), pack_half2(vv.z, vv.w));
    *(uint2*)&g_X16[off]            = qp;
    *(uint2*)&g_X16[M_*D_ + off]    = kp;
    *(uint2*)&g_X16[2*M_*D_ + off]  = vp;

    float sq = qv.x + qv.y + qv.z + qv.w;
    float sk = kv.x + kv.y + kv.z + kv.w;
    sq = warp_sum32(sq);
    sk = warp_sum32(sk);
    __shared__ float rq[4], rk[4];
    int wid = tid >> 5, lane = tid & 31;
    if (lane == 0) { rq[wid] = sq; rk[wid] = sk; }
    __syncthreads();
    if (tid == 0) {
        float tq = rq[0]+rq[1]+rq[2]+rq[3];
        float tk = rk[0]+rk[1]+rk[2]+rk[3];
        g_qmask[row] = (tq != 0.0f) ? 1.0f : 0.0f;
        g_kmask16[row] = __float2half((tk != 0.0f) ? SHIFT_L2 : -10000.0f);
    }
}

// ---------------- W conversion fp32 -> fp16 (Wq scaled by log2e/8) -------------
__global__ __launch_bounds__(256) void wconv_kernel(const float* __restrict__ Wq,
                                                    const float* __restrict__ Wk,
                                                    const float* __restrict__ Wv) {
    int z = blockIdx.y;
    const float* W = (z == 0) ? Wq : (z == 1) ? Wk : Wv;
    float sc = (z == 0) ? QK_LOG2E_8 : 1.0f;
    int idx = blockIdx.x*2048 + threadIdx.x*8;
    float4 a = *(const float4*)&W[idx];
    float4 b = *(const float4*)&W[idx + 4];
    uint4 p;
    p.x = pack_half2(a.x*sc, a.y*sc);
    p.y = pack_half2(a.z*sc, a.w*sc);
    p.z = pack_half2(b.x*sc, b.y*sc);
    p.w = pack_half2(b.z*sc, b.w*sc);
    *(uint4*)&g_W16[(size_t)z*D_*D_ + idx] = p;
}

// ---------------- QKV projection: fp16 HMMA GEMM + bias + relu ---------------
// 3-stage cp.async pipeline. CTA tile 128x128, BK=32.
#define XP 80     // X tile pitch bytes (32 halves + pad)
#define WP 272    // W tile pitch bytes (128 halves + pad)
#define QKV_XB(bs) ((bs)*10240)
#define QKV_WB(bs) (30720 + (bs)*8704)
#define QKV_SMEM   56832

__global__ __launch_bounds__(256) void qkv_hmma(const float* __restrict__ bq,
                                                const float* __restrict__ bk,
                                                const float* __restrict__ bv) {
    __shared__ char smem[QKV_SMEM];
    const uint32_t sbase = s2u(smem);
    int tid = threadIdx.x;
    int wid = tid >> 5, lane = tid & 31;
    int wm = wid & 3, wn = wid >> 2;
    int z = blockIdx.z;
    int nBase = blockIdx.x * 128;
    int mBase = blockIdx.y * 128;

    const __half* Xg = g_X16 + (size_t)z*M_*D_;
    const __half* Wg = g_W16 + (size_t)z*D_*D_;
    const float* bias = (z == 0) ? bq : (z == 1) ? bk : bv;
    float bsc = (z == 0) ? QK_LOG2E_8 : 1.0f;
    __half* Out = (z == 0) ? g_Q16 : (z == 1) ? g_K16 : g_V16;

    auto prefetch = [&](int chunk, int bs) {
        int k0 = chunk * 32;
        uint32_t xd = sbase + QKV_XB(bs);
        uint32_t wd = sbase + QKV_WB(bs);
        #pragma unroll
        for (int r = 0; r < 2; r++) {
            int c = tid + r*256;
            int row = c >> 2, cc = c & 3;
            cp16(xd + row*XP + cc*16, Xg + (size_t)(mBase + row)*D_ + k0 + cc*8);
        }
        #pragma unroll
        for (int r = 0; r < 2; r++) {
            int c = tid + r*256;
            int row = c >> 4, cc = c & 15;
            cp16(wd + row*WP + cc*16, Wg + (size_t)(k0 + row)*D_ + nBase + cc*8);
        }
        CP_COMMIT();
    };

    const uint32_t aLane = (uint32_t)((wm*32 + (lane & 15))*XP + (lane >> 4)*16);
    const uint32_t bLane = (uint32_t)(((lane & 7) + ((lane >> 3) & 1)*8)*WP
                          + (lane >> 4)*16 + wn*128);

    float acc[2][8][4];
    #pragma unroll
    for (int i = 0; i < 2; i++)
        #pragma unroll
        for (int j = 0; j < 8; j++)
            #pragma unroll
            for (int k = 0; k < 4; k++) acc[i][j][k] = 0.f;

    prefetch(0, 0);
    prefetch(1, 1);
    prefetch(2, 2);

    int bs = 0;
    for (int t = 0; t < 16; t++) {
        if (t < 14)      { CP_WAIT(2); }
        else if (t == 14){ CP_WAIT(1); }
        else             { CP_WAIT(0); }
        __syncthreads();
        uint32_t sX = sbase + QKV_XB(bs);
        uint32_t sW = sbase + QKV_WB(bs);
        #pragma unroll
        for (int ks = 0; ks < 2; ks++) {
            uint32_t a0[4], a1[4];
            ldsm4(a0, sX + aLane + ks*32);
            ldsm4(a1, sX + aLane + 16*XP + ks*32);
            #pragma unroll
            for (int nt = 0; nt < 4; nt++) {
                uint32_t b4[4];
                ldsm4t(b4, sW + bLane + ks*16*WP + nt*32);
                mma16816(acc[0][2*nt],   a0, b4[0], b4[1]);
                mma16816(acc[0][2*nt+1], a0, b4[2], b4[3]);
                mma16816(acc[1][2*nt],   a1, b4[0], b4[1]);
                mma16816(acc[1][2*nt+1], a1, b4[2], b4[3]);
            }
        }
        __syncthreads();
        if (t < 13) prefetch(t + 3, bs);
        bs = (bs == 2) ? 0 : bs + 1;
    }

    #pragma unroll
    for (int mt = 0; mt < 2; mt++) {
        int r0 = mBase + wm*32 + mt*16 + (lane >> 2);
        #pragma unroll
        for (int j = 0; j < 8; j++) {
            int col = nBase + wn*64 + (j >> 1)*16 + (j & 1)*8 + (lane & 3)*2;
            float2 bb = *(const float2*)&bias[col];
            bb.x *= bsc; bb.y *= bsc;
            float v0 = fmaxf(acc[mt][j][0] + bb.x, 0.f);
            float v1 = fmaxf(acc[mt][j][1] + bb.y, 0.f);
            float v2 = fmaxf(acc[mt][j][2] + bb.x, 0.f);
            float v3 = fmaxf(acc[mt][j][3] + bb.y, 0.f);
            *(uint32_t*)&Out[(size_t)r0*D_ + col]       = pack_half2(v0, v1);
            *(uint32_t*)&Out[(size_t)(r0+8)*D_ + col]   = pack_half2(v2, v3);
        }
    }
}

// ---------------- V transpose: [b,t, h,d] -> [bh, d, t] -----------------------
__global__ __launch_bounds__(256) void vtrans_kernel() {
    __shared__ __half sm[64][65];
    int bh = blockIdx.x;
    int b = bh / H_, head = bh % H_;
    int t0 = blockIdx.y * 64;
    int tid = threadIdx.x;

    #pragma unroll
    for (int r = 0; r < 2; r++) {
        int idx = tid + r*256;
        int tr = idx >> 3;
        int ch = idx & 7;
        uint4 v = *(const uint4*)(g_V16 + (size_t)(b*T_ + t0 + tr)*D_ + head*DH + ch*8);
        const __half* hp = (const __half*)&v;
        #pragma unroll
        for (int i = 0; i < 8; i++) sm[tr][ch*8 + i] = hp[i];
    }
    __syncthreads();
    #pragma unroll
    for (int r = 0; r < 2; r++) {
        int idx = tid + r*256;
        int d = idx >> 3;
        int ch = idx & 7;
        uint4 v;
        __half* hp = (__half*)&v;
        #pragma unroll
        for (int i = 0; i < 8; i++) hp[i] = sm[ch*8 + i][d];
        *(uint4*)(g_V16t + ((size_t)bh*DH + d)*T_ + t0 + ch*8) = v;
    }
}

// ---------------- HMMA flash attention, 32 q-rows per warp --------------------
// 256 thr = 8 warps; warp owns 32 q-rows x 128 keys. Q pre-scaled by log2e/8;
// softmax arg = acc + koff(half2) via HADD2 + ex2.approx.f16x2; l via ones-MMA.
#define AKB(bs)  ((bs)*18432)
#define AVB(bs)  (36864 + (bs)*17408)
#define AKM(bs)  (71680 + (bs)*256)
#define SMEM_ATTN 72192

__global__ __launch_bounds__(256) void attn_kernel() {
    extern __shared__ char smem[];
    const uint32_t sbase = s2u(smem);

    int tid = threadIdx.x;
    int wid = tid >> 5, lane = tid & 31;
    int bh = blockIdx.x;
    int b = bh >> 3, head = bh & 7;
    int qbase = blockIdx.y * 256;
    int qw0 = wid * 32;

    const __half* Qg = g_Q16 + (size_t)(b*T_ + qbase)*D_ + head*DH;
    const __half* Kg = g_K16 + (size_t)(b*T_)*D_ + head*DH;
    const __half* Vg = g_V16t + (size_t)bh*DH*T_;
    const __half* kmg = g_kmask16 + b*T_;

    // ---- stage Q (256 rows) in two 128-row passes through buffer-0 K region --
    uint32_t qa[2][4][4];
    for (int h = 0; h < 2; h++) {
        #pragma unroll
        for (int r = 0; r < 4; r++) {
            int idx = tid + r*256;
            int row = idx >> 3, c = idx & 7;
            *(uint4*)(smem + row*144 + c*16) =
                *(const uint4*)(Qg + (size_t)(h*128 + row)*D_ + c*8);
        }
        __syncthreads();
        if ((wid >> 2) == h) {
            int rloc = qw0 - h*128;
            #pragma unroll
            for (int mt = 0; mt < 2; mt++) {
                uint32_t qaddr = sbase + (uint32_t)(rloc + mt*16 + (lane & 15))*144
                               + (uint32_t)(lane >> 4)*16;
                #pragma unroll
                for (int s = 0; s < 4; s++) ldsm4(qa[mt][s], qaddr + s*32);
            }
        }
        __syncthreads();
    }

    auto prefetch = [&](int t, int bs) {
        int kb = t * 128;
        uint32_t kd = sbase + AKB(bs);
        uint32_t vd = sbase + AVB(bs);
        #pragma unroll
        for (int r = 0; r < 4; r++) {
            int idx = tid + r*256;
            int row = idx >> 3, c = idx & 7;
            cp16(kd + row*144 + c*16, Kg + (size_t)(kb + row)*D_ + c*8);
        }
        #pragma unroll
        for (int r = 0; r < 4; r++) {
            int idx = tid + r*256;
            int d = idx >> 4, c = idx & 15;
            cp16(vd + d*272 + c*16, Vg + (size_t)d*T_ + kb + c*8);
        }
        if (tid < 16) cp16(sbase + AKM(bs) + tid*16, kmg + kb + tid*8);
        CP_COMMIT();
    };

    const uint32_t kLane = (uint32_t)((lane & 7) + ((lane >> 4) << 3))*144
                         + (uint32_t)((lane >> 3) & 1)*16;
    const uint32_t vLane = (uint32_t)((lane & 7) + ((lane >> 4) << 3))*272
                         + (uint32_t)((lane >> 3) & 1)*16;

    float oacc[2][8][4];
    #pragma unroll
    for (int m = 0; m < 2; m++)
        #pragma unroll
        for (int i = 0; i < 8; i++)
            #pragma unroll
            for (int j = 0; j < 4; j++) oacc[m][i][j] = 0.f;
    float lacc[2][4];
    #pragma unroll
    for (int m = 0; m < 2; m++)
        #pragma unroll
        for (int j = 0; j < 4; j++) lacc[m][j] = 0.f;

    prefetch(0, 0);
    prefetch(1, 1);

    for (int t = 0; t < 16; t++) {
        if (t < 15) { CP_WAIT(1); } else { CP_WAIT(0); }
        __syncthreads();
        int bs = t & 1;
        uint32_t kaddr0 = sbase + AKB(bs) + kLane;
        uint32_t vaddr0 = sbase + AVB(bs) + vLane;
        const __half* kof16 = (const __half*)(smem + AKM(bs));

        // ---- process 128 keys in four 32-key chunks ----
        #pragma unroll
        for (int c = 0; c < 4; c++) {
            float acc[2][4][4];
            #pragma unroll
            for (int m = 0; m < 2; m++)
                #pragma unroll
                for (int g = 0; g < 4; g++)
                    #pragma unroll
                    for (int x = 0; x < 4; x++) acc[m][g][x] = 0.f;

            #pragma unroll
            for (int j = 0; j < 2; j++) {
                #pragma unroll
                for (int s = 0; s < 4; s++) {
                    uint32_t kb4[4];
                    ldsm4(kb4, kaddr0 + (uint32_t)((c*32 + j*16))*144 + s*32);
                    mma16816(acc[0][2*j],   qa[0][s], kb4[0], kb4[1]);
                    mma16816(acc[0][2*j+1], qa[0][s], kb4[2], kb4[3]);
                    mma16816(acc[1][2*j],   qa[1][s], kb4[0], kb4[1]);
                    mma16816(acc[1][2*j+1], qa[1][s], kb4[2], kb4[3]);
                }
            }

            // softmax: arg = acc + koff(half2); p via ex2.f16x2; l via ones-MMA
            #pragma unroll
            for (int j = 0; j < 2; j++) {
                int jg = c*2 + j;
                uint32_t ka2 = *(const uint32_t*)(kof16 + jg*16 + (lane & 3)*2);
                uint32_t kb2 = *(const uint32_t*)(kof16 + jg*16 + 8 + (lane & 3)*2);
                uint32_t pa[2][4];
                #pragma unroll
                for (int mt = 0; mt < 2; mt++) {
                    pa[mt][0] = exp2_h2_add(acc[mt][2*j][0],   acc[mt][2*j][1],   ka2);
                    pa[mt][1] = exp2_h2_add(acc[mt][2*j][2],   acc[mt][2*j][3],   ka2);
                    pa[mt][2] = exp2_h2_add(acc[mt][2*j+1][0], acc[mt][2*j+1][1], kb2);
                    pa[mt][3] = exp2_h2_add(acc[mt][2*j+1][2], acc[mt][2*j+1][3], kb2);
                    mma16816(lacc[mt], pa[mt], ONES_H2, ONES_H2);
                }
                #pragma unroll
                for (int nd = 0; nd < 4; nd++) {
                    uint32_t vb4[4];
                    ldsm4(vb4, vaddr0 + (uint32_t)(nd*16)*272 + jg*32);
                    mma16816(oacc[0][2*nd],   pa[0], vb4[0], vb4[1]);
                    mma16816(oacc[0][2*nd+1], pa[0], vb4[2], vb4[3]);
                    mma16816(oacc[1][2*nd],   pa[1], vb4[0], vb4[1]);
                    mma16816(oacc[1][2*nd+1], pa[1], vb4[2], vb4[3]);
                }
            }
        }
        __syncthreads();
        if (t < 14) prefetch(t + 2, bs);
    }

    // ---- finalize both m-tiles (l read straight from lacc; no shfls) ----
    #pragma unroll
    for (int mt = 0; mt < 2; mt++) {
        float l0 = lacc[mt][0];
        float l1 = lacc[mt][2];

        int r0 = qbase + qw0 + mt*16 + (lane >> 2);
        int r1 = r0 + 8;
        float f0 = g_qmask[b*T_ + r0] / l0;
        float f1 = g_qmask[b*T_ + r1] / l1;
        float* O0 = g_O + (size_t)(b*T_ + r0)*D_ + head*DH + (lane & 3)*2;
        float* O1 = g_O + (size_t)(b*T_ + r1)*D_ + head*DH + (lane & 3)*2;
        #pragma unroll
        for (int nd = 0; nd < 8; nd++) {
            *(float2*)(O0 + nd*8) = make_float2(oacc[mt][nd][0]*f0, oacc[mt][nd][1]*f0);
            *(float2*)(O1 + nd*8) = make_float2(oacc[mt][nd][2]*f1, oacc[mt][nd][3]*f1);
        }
    }
}

// ---------------- residual + LayerNorm (unbiased std, eps on std) -------------
__global__ __launch_bounds__(128) void ln_kernel(const float* __restrict__ queries,
                                                 const float* __restrict__ gamma,
                                                 const float* __restrict__ beta,
                                                 float* __restrict__ out) {
    int row = blockIdx.x;
    int tid = threadIdx.x;
    const float* o = g_O + (size_t)row*D_;
    const float* q = queries + (size_t)row*D_;
    float4 ov = *(const float4*)&o[tid*4];
    float4 qv = *(const float4*)&q[tid*4];
    float x0 = ov.x + qv.x;
    float x1 = ov.y + qv.y;
    float x2 = ov.z + qv.z;
    float x3 = ov.w + qv.w;
    float s  = x0 + x1 + x2 + x3;
    float ss = x0*x0 + x1*x1 + x2*x2 + x3*x3;
    s  = warp_sum32(s);
    ss = warp_sum32(ss);
    __shared__ float rs[4], rss[4];
    int wid = tid >> 5, lane = tid & 31;
    if (lane == 0) { rs[wid] = s; rss[wid] = ss; }
    __syncthreads();
    float S  = rs[0] + rs[1] + rs[2] + rs[3];
    float SS = rss[0] + rss[1] + rss[2] + rss[3];
    float mean = S * (1.0f / D_);
    float var  = (SS - (float)D_ * mean * mean) * (1.0f / (D_ - 1));
    var = fmaxf(var, 0.f);
    float inv = 1.0f / (sqrtf(var) + LN_EPS);
    float4 gv = *(const float4*)&gamma[tid*4];
    float4 bv = *(const float4*)&beta[tid*4];
    float4 r;
    r.x = gv.x * (x0 - mean) * inv + bv.x;
    r.y = gv.y * (x1 - mean) * inv + bv.y;
    r.z = gv.z * (x2 - mean) * inv + bv.z;
    r.w = gv.w * (x3 - mean) * inv + bv.w;
    *(float4*)&out[(size_t)row*D_ + tid*4] = r;
}

// ---------------- launch ------------------------------------------------------
extern "C" void kernel_launch(void* const* d_in, const int* in_sizes, int n_in,
                              void* d_out, int out_size) {
    const float* queries = (const float*)d_in[0];
    const float* keys    = (const float*)d_in[1];
    const float* values  = (const float*)d_in[2];
    const float* Wq = (const float*)d_in[3];
    const float* bq = (const float*)d_in[4];
    const float* Wk = (const float*)d_in[5];
    const float* bk = (const float*)d_in[6];
    const float* Wv = (const float*)d_in[7];
    const float* bv = (const float*)d_in[8];
    const float* gamma = (const float*)d_in[9];
    const float* beta  = (const float*)d_in[10];
    float* out = (float*)d_out;

    cudaFuncSetAttribute(attn_kernel, cudaFuncAttributeMaxDynamicSharedMemorySize, SMEM_ATTN);

    prep_kernel<<<M_, 128>>>(queries, keys, values);
    wconv_kernel<<<dim3(128, 3), 256>>>(Wq, Wk, Wv);
    qkv_hmma<<<dim3(4, 64, 3), 256>>>(bq, bk, bv);
    vtrans_kernel<<<dim3(B_*H_, T_/64), 256>>>();
    attn_kernel<<<dim3(B_*H_, T_/256), 256, SMEM_ATTN>>>();
    ln_kernel<<<M_, 128>>>(queries, gamma, beta, out);
}

// round 17
// speedup vs baseline: 1.0435x; 1.0435x over previous
#include <cuda_runtime.h>
#include <cuda_fp16.h>
#include <cstdint>

#define B_ 4
#define T_ 2048
#define D_ 512
#define H_ 8
#define DH 64
#define M_ (B_*T_)              // 8192 rows
#define LN_EPS 1e-8f

// exp(s/8 - 5) = 2^(s*log2e/8 - 5*log2e); the s*log2e/8 factor is folded into Wq/bq.
#define QK_LOG2E_8 0.1803368801111204f
#define SHIFT_L2   (-7.2134752044448169f)

// ---------------- scratch (device globals: no allocation allowed) -------------
__device__ __half g_X16[3*M_*D_];        // fp16 queries/keys/values
__device__ __half g_W16[3*D_*D_];        // fp16 Wq(scaled)/Wk/Wv
__device__ __half g_Q16[M_*D_];          // pre-scaled by log2e/8
__device__ __half g_K16[M_*D_];
__device__ __half g_V16[M_*D_];
__device__ float  g_O[M_*D_];
__device__ float  g_qmask[M_];
__device__ __half g_kmask16[M_];         // exp2-domain offset: SHIFT_L2 or -1e4

// ---------------- helpers -----------------------------------------------------
__device__ __forceinline__ float warp_sum32(float v) {
    #pragma unroll
    for (int o = 16; o > 0; o >>= 1) v += __shfl_xor_sync(0xffffffffu, v, o);
    return v;
}

__device__ __forceinline__ uint32_t s2u(const void* p) {
    uint32_t a;
    asm("{ .reg .u64 t; cvta.to.shared.u64 t, %1; cvt.u32.u64 %0, t; }" : "=r"(a) : "l"(p));
    return a;
}

__device__ __forceinline__ uint32_t pack_half2(float lo, float hi) {
    uint32_t r;
    asm("cvt.rn.f16x2.f32 %0, %1, %2;" : "=r"(r) : "f"(hi), "f"(lo));
    return r;
}

// p = 2^(s + koff) for two packed values: CVT + HADD2 + MUFU
__device__ __forceinline__ uint32_t exp2_h2_add(float lo, float hi, uint32_t off2) {
    uint32_t h = pack_half2(lo, hi);
    uint32_t s, r;
    asm("add.rn.f16x2 %0, %1, %2;" : "=r"(s) : "r"(h), "r"(off2));
    asm("ex2.approx.f16x2 %0, %1;" : "=r"(r) : "r"(s));
    return r;
}

#define ONES_H2 0x3C003C00u   // half2(1.0, 1.0)

__device__ __forceinline__ void ldsm4(uint32_t* r, uint32_t addr) {
    asm volatile("ldmatrix.sync.aligned.m8n8.x4.shared.b16 {%0,%1,%2,%3}, [%4];"
        : "=r"(r[0]), "=r"(r[1]), "=r"(r[2]), "=r"(r[3]) : "r"(addr));
}

__device__ __forceinline__ void ldsm4t(uint32_t* r, uint32_t addr) {
    asm volatile("ldmatrix.sync.aligned.m8n8.x4.trans.shared.b16 {%0,%1,%2,%3}, [%4];"
        : "=r"(r[0]), "=r"(r[1]), "=r"(r[2]), "=r"(r[3]) : "r"(addr));
}

__device__ __forceinline__ void mma16816(float* c, const uint32_t* a,
                                         uint32_t b0, uint32_t b1) {
    asm volatile(
        "mma.sync.aligned.m16n8k16.row.col.f32.f16.f16.f32 "
        "{%0,%1,%2,%3}, {%4,%5,%6,%7}, {%8,%9}, {%0,%1,%2,%3};"
        : "+f"(c[0]), "+f"(c[1]), "+f"(c[2]), "+f"(c[3])
        : "r"(a[0]), "r"(a[1]), "r"(a[2]), "r"(a[3]), "r"(b0), "r"(b1));
}

__device__ __forceinline__ void cp16(uint32_t smem_dst, const void* gsrc) {
    asm volatile("cp.async.cg.shared.global [%0], [%1], 16;"
        :: "r"(smem_dst), "l"(__cvta_generic_to_global(gsrc)) : "memory");
}
#define CP_COMMIT() asm volatile("cp.async.commit_group;" ::: "memory")
#define CP_WAIT(n)  asm volatile("cp.async.wait_group %0;" :: "n"(n) : "memory")

// ---------------- prep: fp32 -> fp16 X + masks --------------------------------
__global__ __launch_bounds__(128) void prep_kernel(const float* __restrict__ queries,
                                                   const float* __restrict__ keys,
                                                   const float* __restrict__ values) {
    int row = blockIdx.x;
    int tid = threadIdx.x;
    size_t off = (size_t)row*D_ + tid*4;
    float4 qv = *(const float4*)&queries[off];
    float4 kv = *(const float4*)&keys[off];
    float4 vv = *(const float4*)&values[off];
    uint2 qp = make_uint2(pack_half2(qv.x, qv.y), pack_half2(qv.z, qv.w));
    uint2 kp = make_uint2(pack_half2(kv.x, kv.y), pack_half2(kv.z, kv.w));
    uint2 vp = make_uint2(pack_half2(vv.x, vv.y), pack_half2(vv.z, vv.w));
    *(uint2*)&g_X16[off]            = qp;
    *(uint2*)&g_X16[M_*D_ + off]    = kp;
    *(uint2*)&g_X16[2*M_*D_ + off]  = vp;

    float sq = qv.x + qv.y + qv.z + qv.w;
    float sk = kv.x + kv.y + kv.z + kv.w;
    sq = warp_sum32(sq);
    sk = warp_sum32(sk);
    __shared__ float rq[4], rk[4];
    int wid = tid >> 5, lane = tid & 31;
    if (lane == 0) { rq[wid] = sq; rk[wid] = sk; }
    __syncthreads();
    if (tid == 0) {
        float tq = rq[0]+rq[1]+rq[2]+rq[3];
        float tk = rk[0]+rk[1]+rk[2]+rk[3];
        g_qmask[row] = (tq != 0.0f) ? 1.0f : 0.0f;
        g_kmask16[row] = __float2half((tk != 0.0f) ? SHIFT_L2 : -10000.0f);
    }
}

// ---------------- W conversion fp32 -> fp16 (Wq scaled by log2e/8) -------------
__global__ __launch_bounds__(256) void wconv_kernel(const float* __restrict__ Wq,
                                                    const float* __restrict__ Wk,
                                                    const float* __restrict__ Wv) {
    int z = blockIdx.y;
    const float* W = (z == 0) ? Wq : (z == 1) ? Wk : Wv;
    float sc = (z == 0) ? QK_LOG2E_8 : 1.0f;
    int idx = blockIdx.x*2048 + threadIdx.x*8;
    float4 a = *(const float4*)&W[idx];
    float4 b = *(const float4*)&W[idx + 4];
    uint4 p;
    p.x = pack_half2(a.x*sc, a.y*sc);
    p.y = pack_half2(a.z*sc, a.w*sc);
    p.z = pack_half2(b.x*sc, b.y*sc);
    p.w = pack_half2(b.z*sc, b.w*sc);
    *(uint4*)&g_W16[(size_t)z*D_*D_ + idx] = p;
}

// ---------------- QKV projection: fp16 HMMA GEMM + bias + relu ---------------
// 3-stage cp.async pipeline. CTA tile 128x128, BK=32.
#define XP 80     // X tile pitch bytes (32 halves + pad)
#define WP 272    // W tile pitch bytes (128 halves + pad)
#define QKV_XB(bs) ((bs)*10240)
#define QKV_WB(bs) (30720 + (bs)*8704)
#define QKV_SMEM   56832

__global__ __launch_bounds__(256) void qkv_hmma(const float* __restrict__ bq,
                                                const float* __restrict__ bk,
                                                const float* __restrict__ bv) {
    __shared__ char smem[QKV_SMEM];
    const uint32_t sbase = s2u(smem);
    int tid = threadIdx.x;
    int wid = tid >> 5, lane = tid & 31;
    int wm = wid & 3, wn = wid >> 2;
    int z = blockIdx.z;
    int nBase = blockIdx.x * 128;
    int mBase = blockIdx.y * 128;

    const __half* Xg = g_X16 + (size_t)z*M_*D_;
    const __half* Wg = g_W16 + (size_t)z*D_*D_;
    const float* bias = (z == 0) ? bq : (z == 1) ? bk : bv;
    float bsc = (z == 0) ? QK_LOG2E_8 : 1.0f;
    __half* Out = (z == 0) ? g_Q16 : (z == 1) ? g_K16 : g_V16;

    auto prefetch = [&](int chunk, int bs) {
        int k0 = chunk * 32;
        uint32_t xd = sbase + QKV_XB(bs);
        uint32_t wd = sbase + QKV_WB(bs);
        #pragma unroll
        for (int r = 0; r < 2; r++) {
            int c = tid + r*256;
            int row = c >> 2, cc = c & 3;
            cp16(xd + row*XP + cc*16, Xg + (size_t)(mBase + row)*D_ + k0 + cc*8);
        }
        #pragma unroll
        for (int r = 0; r < 2; r++) {
            int c = tid + r*256;
            int row = c >> 4, cc = c & 15;
            cp16(wd + row*WP + cc*16, Wg + (size_t)(k0 + row)*D_ + nBase + cc*8);
        }
        CP_COMMIT();
    };

    const uint32_t aLane = (uint32_t)((wm*32 + (lane & 15))*XP + (lane >> 4)*16);
    const uint32_t bLane = (uint32_t)(((lane & 7) + ((lane >> 3) & 1)*8)*WP
                          + (lane >> 4)*16 + wn*128);

    float acc[2][8][4];
    #pragma unroll
    for (int i = 0; i < 2; i++)
        #pragma unroll
        for (int j = 0; j < 8; j++)
            #pragma unroll
            for (int k = 0; k < 4; k++) acc[i][j][k] = 0.f;

    prefetch(0, 0);
    prefetch(1, 1);
    prefetch(2, 2);

    int bs = 0;
    for (int t = 0; t < 16; t++) {
        if (t < 14)      { CP_WAIT(2); }
        else if (t == 14){ CP_WAIT(1); }
        else             { CP_WAIT(0); }
        __syncthreads();
        uint32_t sX = sbase + QKV_XB(bs);
        uint32_t sW = sbase + QKV_WB(bs);
        #pragma unroll
        for (int ks = 0; ks < 2; ks++) {
            uint32_t a0[4], a1[4];
            ldsm4(a0, sX + aLane + ks*32);
            ldsm4(a1, sX + aLane + 16*XP + ks*32);
            #pragma unroll
            for (int nt = 0; nt < 4; nt++) {
                uint32_t b4[4];
                ldsm4t(b4, sW + bLane + ks*16*WP + nt*32);
                mma16816(acc[0][2*nt],   a0, b4[0], b4[1]);
                mma16816(acc[0][2*nt+1], a0, b4[2], b4[3]);
                mma16816(acc[1][2*nt],   a1, b4[0], b4[1]);
                mma16816(acc[1][2*nt+1], a1, b4[2], b4[3]);
            }
        }
        __syncthreads();
        if (t < 13) prefetch(t + 3, bs);
        bs = (bs == 2) ? 0 : bs + 1;
    }

    #pragma unroll
    for (int mt = 0; mt < 2; mt++) {
        int r0 = mBase + wm*32 + mt*16 + (lane >> 2);
        #pragma unroll
        for (int j = 0; j < 8; j++) {
            int col = nBase + wn*64 + (j >> 1)*16 + (j & 1)*8 + (lane & 3)*2;
            float2 bb = *(const float2*)&bias[col];
            bb.x *= bsc; bb.y *= bsc;
            float v0 = fmaxf(acc[mt][j][0] + bb.x, 0.f);
            float v1 = fmaxf(acc[mt][j][1] + bb.y, 0.f);
            float v2 = fmaxf(acc[mt][j][2] + bb.x, 0.f);
            float v3 = fmaxf(acc[mt][j][3] + bb.y, 0.f);
            *(uint32_t*)&Out[(size_t)r0*D_ + col]       = pack_half2(v0, v1);
            *(uint32_t*)&Out[(size_t)(r0+8)*D_ + col]   = pack_half2(v2, v3);
        }
    }
}

// ---------------- HMMA flash attention, 32 q-rows per warp --------------------
// 256 thr = 8 warps; warp owns 32 q-rows x 128 keys. V tile row-major [t,d]
// (same layout as K); PV B-frags via ldmatrix.trans — no vtrans kernel.
#define AKB(bs)  ((bs)*18432)
#define AVB(bs)  (36864 + (bs)*18432)
#define AKM(bs)  (73728 + (bs)*256)
#define SMEM_ATTN 74240

__global__ __launch_bounds__(256) void attn_kernel() {
    extern __shared__ char smem[];
    const uint32_t sbase = s2u(smem);

    int tid = threadIdx.x;
    int wid = tid >> 5, lane = tid & 31;
    int bh = blockIdx.x;
    int b = bh >> 3, head = bh & 7;
    int qbase = blockIdx.y * 256;
    int qw0 = wid * 32;

    const __half* Qg = g_Q16 + (size_t)(b*T_ + qbase)*D_ + head*DH;
    const __half* Kg = g_K16 + (size_t)(b*T_)*D_ + head*DH;
    const __half* Vg = g_V16 + (size_t)(b*T_)*D_ + head*DH;
    const __half* kmg = g_kmask16 + b*T_;

    // ---- stage Q (256 rows) in two 128-row passes through buffer-0 K region --
    uint32_t qa[2][4][4];
    for (int h = 0; h < 2; h++) {
        #pragma unroll
        for (int r = 0; r < 4; r++) {
            int idx = tid + r*256;
            int row = idx >> 3, c = idx & 7;
            *(uint4*)(smem + row*144 + c*16) =
                *(const uint4*)(Qg + (size_t)(h*128 + row)*D_ + c*8);
        }
        __syncthreads();
        if ((wid >> 2) == h) {
            int rloc = qw0 - h*128;
            #pragma unroll
            for (int mt = 0; mt < 2; mt++) {
                uint32_t qaddr = sbase + (uint32_t)(rloc + mt*16 + (lane & 15))*144
                               + (uint32_t)(lane >> 4)*16;
                #pragma unroll
                for (int s = 0; s < 4; s++) ldsm4(qa[mt][s], qaddr + s*32);
            }
        }
        __syncthreads();
    }

    auto prefetch = [&](int t, int bs) {
        int kb = t * 128;
        uint32_t kd = sbase + AKB(bs);
        uint32_t vd = sbase + AVB(bs);
        #pragma unroll
        for (int r = 0; r < 4; r++) {
            int idx = tid + r*256;
            int row = idx >> 3, c = idx & 7;
            cp16(kd + row*144 + c*16, Kg + (size_t)(kb + row)*D_ + c*8);
        }
        #pragma unroll
        for (int r = 0; r < 4; r++) {
            int idx = tid + r*256;
            int row = idx >> 3, c = idx & 7;
            cp16(vd + row*144 + c*16, Vg + (size_t)(kb + row)*D_ + c*8);
        }
        if (tid < 16) cp16(sbase + AKM(bs) + tid*16, kmg + kb + tid*8);
        CP_COMMIT();
    };

    const uint32_t kLane = (uint32_t)((lane & 7) + ((lane >> 4) << 3))*144
                         + (uint32_t)((lane >> 3) & 1)*16;
    // trans-load lane base for V (row-major [t,d] tile): t = (lane&7)+((lane>>3)&1)*8,
    // d-halfblock = lane>>4
    const uint32_t vLane = (uint32_t)((lane & 7) + ((lane >> 3) & 1)*8)*144
                         + (uint32_t)(lane >> 4)*16;

    float oacc[2][8][4];
    #pragma unroll
    for (int m = 0; m < 2; m++)
        #pragma unroll
        for (int i = 0; i < 8; i++)
            #pragma unroll
            for (int j = 0; j < 4; j++) oacc[m][i][j] = 0.f;
    float lacc[2][4];
    #pragma unroll
    for (int m = 0; m < 2; m++)
        #pragma unroll
        for (int j = 0; j < 4; j++) lacc[m][j] = 0.f;

    prefetch(0, 0);
    prefetch(1, 1);

    for (int t = 0; t < 16; t++) {
        if (t < 15) { CP_WAIT(1); } else { CP_WAIT(0); }
        __syncthreads();
        int bs = t & 1;
        uint32_t kaddr0 = sbase + AKB(bs) + kLane;
        uint32_t vaddr0 = sbase + AVB(bs) + vLane;
        const __half* kof16 = (const __half*)(smem + AKM(bs));

        // ---- process 128 keys in four 32-key chunks ----
        #pragma unroll
        for (int c = 0; c < 4; c++) {
            float acc[2][4][4];
            #pragma unroll
            for (int m = 0; m < 2; m++)
                #pragma unroll
                for (int g = 0; g < 4; g++)
                    #pragma unroll
                    for (int x = 0; x < 4; x++) acc[m][g][x] = 0.f;

            #pragma unroll
            for (int j = 0; j < 2; j++) {
                #pragma unroll
                for (int s = 0; s < 4; s++) {
                    uint32_t kb4[4];
                    ldsm4(kb4, kaddr0 + (uint32_t)((c*32 + j*16))*144 + s*32);
                    mma16816(acc[0][2*j],   qa[0][s], kb4[0], kb4[1]);
                    mma16816(acc[0][2*j+1], qa[0][s], kb4[2], kb4[3]);
                    mma16816(acc[1][2*j],   qa[1][s], kb4[0], kb4[1]);
                    mma16816(acc[1][2*j+1], qa[1][s], kb4[2], kb4[3]);
                }
            }

            // softmax: arg = acc + koff(half2); p via ex2.f16x2; l via ones-MMA
            #pragma unroll
            for (int j = 0; j < 2; j++) {
                int jg = c*2 + j;
                uint32_t ka2 = *(const uint32_t*)(kof16 + jg*16 + (lane & 3)*2);
                uint32_t kb2 = *(const uint32_t*)(kof16 + jg*16 + 8 + (lane & 3)*2);
                uint32_t pa[2][4];
                #pragma unroll
                for (int mt = 0; mt < 2; mt++) {
                    pa[mt][0] = exp2_h2_add(acc[mt][2*j][0],   acc[mt][2*j][1],   ka2);
                    pa[mt][1] = exp2_h2_add(acc[mt][2*j][2],   acc[mt][2*j][3],   ka2);
                    pa[mt][2] = exp2_h2_add(acc[mt][2*j+1][0], acc[mt][2*j+1][1], kb2);
                    pa[mt][3] = exp2_h2_add(acc[mt][2*j+1][2], acc[mt][2*j+1][3], kb2);
                    mma16816(lacc[mt], pa[mt], ONES_H2, ONES_H2);
                }
                #pragma unroll
                for (int nd = 0; nd < 4; nd++) {
                    uint32_t vb4[4];
                    ldsm4t(vb4, vaddr0 + (uint32_t)(jg*16)*144 + nd*32);
                    mma16816(oacc[0][2*nd],   pa[0], vb4[0], vb4[1]);
                    mma16816(oacc[0][2*nd+1], pa[0], vb4[2], vb4[3]);
                    mma16816(oacc[1][2*nd],   pa[1], vb4[0], vb4[1]);
                    mma16816(oacc[1][2*nd+1], pa[1], vb4[2], vb4[3]);
                }
            }
        }
        __syncthreads();
        if (t < 14) prefetch(t + 2, bs);
    }

    // ---- finalize both m-tiles (l read straight from lacc; no shfls) ----
    #pragma unroll
    for (int mt = 0; mt < 2; mt++) {
        float l0 = lacc[mt][0];
        float l1 = lacc[mt][2];

        int r0 = qbase + qw0 + mt*16 + (lane >> 2);
        int r1 = r0 + 8;
        float f0 = g_qmask[b*T_ + r0] / l0;
        float f1 = g_qmask[b*T_ + r1] / l1;
        float* O0 = g_O + (size_t)(b*T_ + r0)*D_ + head*DH + (lane & 3)*2;
        float* O1 = g_O + (size_t)(b*T_ + r1)*D_ + head*DH + (lane & 3)*2;
        #pragma unroll
        for (int nd = 0; nd < 8; nd++) {
            *(float2*)(O0 + nd*8) = make_float2(oacc[mt][nd][0]*f0, oacc[mt][nd][1]*f0);
            *(float2*)(O1 + nd*8) = make_float2(oacc[mt][nd][2]*f1, oacc[mt][nd][3]*f1);
        }
    }
}

// ---------------- residual + LayerNorm (unbiased std, eps on std) -------------
__global__ __launch_bounds__(128) void ln_kernel(const float* __restrict__ queries,
                                                 const float* __restrict__ gamma,
                                                 const float* __restrict__ beta,
                                                 float* __restrict__ out) {
    int row = blockIdx.x;
    int tid = threadIdx.x;
    const float* o = g_O + (size_t)row*D_;
    const float* q = queries + (size_t)row*D_;
    float4 ov = *(const float4*)&o[tid*4];
    float4 qv = *(const float4*)&q[tid*4];
    float x0 = ov.x + qv.x;
    float x1 = ov.y + qv.y;
    float x2 = ov.z + qv.z;
    float x3 = ov.w + qv.w;
    float s  = x0 + x1 + x2 + x3;
    float ss = x0*x0 + x1*x1 + x2*x2 + x3*x3;
    s  = warp_sum32(s);
    ss = warp_sum32(ss);
    __shared__ float rs[4], rss[4];
    int wid = tid >> 5, lane = tid & 31;
    if (lane == 0) { rs[wid] = s; rss[wid] = ss; }
    __syncthreads();
    float S  = rs[0] + rs[1] + rs[2] + rs[3];
    float SS = rss[0] + rss[1] + rss[2] + rss[3];
    float mean = S * (1.0f / D_);
    float var  = (SS - (float)D_ * mean * mean) * (1.0f / (D_ - 1));
    var = fmaxf(var, 0.f);
    float inv = 1.0f / (sqrtf(var) + LN_EPS);
    float4 gv = *(const float4*)&gamma[tid*4];
    float4 bv = *(const float4*)&beta[tid*4];
    float4 r;
    r.x = gv.x * (x0 - mean) * inv + bv.x;
    r.y = gv.y * (x1 - mean) * inv + bv.y;
    r.z = gv.z * (x2 - mean) * inv + bv.z;
    r.w = gv.w * (x3 - mean) * inv + bv.w;
    *(float4*)&out[(size_t)row*D_ + tid*4] = r;
}

// ---------------- launch ------------------------------------------------------
extern "C" void kernel_launch(void* const* d_in, const int* in_sizes, int n_in,
                              void* d_out, int out_size) {
    const float* queries = (const float*)d_in[0];
    const float* keys    = (const float*)d_in[1];
    const float* values  = (const float*)d_in[2];
    const float* Wq = (const float*)d_in[3];
    const float* bq = (const float*)d_in[4];
    const float* Wk = (const float*)d_in[5];
    const float* bk = (const float*)d_in[6];
    const float* Wv = (const float*)d_in[7];
    const float* bv = (const float*)d_in[8];
    const float* gamma = (const float*)d_in[9];
    const float* beta  = (const float*)d_in[10];
    float* out = (float*)d_out;

    cudaFuncSetAttribute(attn_kernel, cudaFuncAttributeMaxDynamicSharedMemorySize, SMEM_ATTN);

    prep_kernel<<<M_, 128>>>(queries, keys, values);
    wconv_kernel<<<dim3(128, 3), 256>>>(Wq, Wk, Wv);
    qkv_hmma<<<dim3(4, 64, 3), 256>>>(bq, bk, bv);
    attn_kernel<<<dim3(B_*H_, T_/256), 256, SMEM_ATTN>>>();
    ln_kernel<<<M_, 128>>>(queries, gamma, beta, out);
}